// round 1
// baseline (speedup 1.0000x reference)
#include <cuda_runtime.h>
#include <cuda_bf16.h>
#include <cstddef>

// ---------------------------------------------------------------------------
// Transformer forward (encoder-decoder), fp32 baseline.
// B=2, S_SRC=S_TGT=512, D=1024, H=16, DK=64, DFF=4096, L=4.
// Output layout (fp32): [dec_out (B*S*D)] [enc_attns (L*B*H*S*S)]
//                       [self_attns (...)] [cross_attns (...)]
// ---------------------------------------------------------------------------

#define BB   2
#define SS   512
#define DD   1024
#define HH   16
#define DKK  64
#define DFFF 4096
#define LL   4
#define MROWS (BB*SS)          // 1024
#define EPSF 1e-5f
// SCALE = sqrt(DK) = 8
#define INV_SCALE 0.125f

// Scratch: 19M floats = 76 MB
static const size_t MEG = 1u << 20;
__device__ float g_scratch[19u * (1u << 20)];

// ---------------------------------------------------------------------------
// Generic tiled GEMM: C[M,N] = A[M,K] @ W[K,N] + bias[N], optional ReLU.
// 64x64 tile, 256 threads, 4x4 per thread, K-step 16.
// ---------------------------------------------------------------------------
__global__ __launch_bounds__(256)
void gemm_bias_kernel(const float* __restrict__ A,
                      const float* __restrict__ W,
                      const float* __restrict__ bias,
                      float* __restrict__ C,
                      int M, int N, int K, int relu)
{
    __shared__ float As[16][65];
    __shared__ float Bs[16][64];
    const int t  = threadIdx.x;
    const int tx = t & 15, ty = t >> 4;
    const int row0 = blockIdx.y * 64, col0 = blockIdx.x * 64;
    float acc[4][4] = {};

    for (int k0 = 0; k0 < K; k0 += 16) {
#pragma unroll
        for (int i = 0; i < 4; i++) {
            int idx = t + i * 256;            // 0..1023
            int ar = idx >> 4, ac = idx & 15; // A tile 64x16
            As[ac][ar] = A[(size_t)(row0 + ar) * K + k0 + ac];
            int br = idx >> 6, bc = idx & 63; // W tile 16x64
            Bs[br][bc] = W[(size_t)(k0 + br) * N + col0 + bc];
        }
        __syncthreads();
#pragma unroll
        for (int kk = 0; kk < 16; kk++) {
            float a[4], b[4];
#pragma unroll
            for (int i = 0; i < 4; i++) a[i] = As[kk][ty * 4 + i];
#pragma unroll
            for (int j = 0; j < 4; j++) b[j] = Bs[kk][tx * 4 + j];
#pragma unroll
            for (int i = 0; i < 4; i++)
#pragma unroll
                for (int j = 0; j < 4; j++)
                    acc[i][j] = fmaf(a[i], b[j], acc[i][j]);
        }
        __syncthreads();
    }

#pragma unroll
    for (int i = 0; i < 4; i++) {
        int r = row0 + ty * 4 + i;
#pragma unroll
        for (int j = 0; j < 4; j++) {
            int c = col0 + tx * 4 + j;
            float v = acc[i][j] + bias[c];
            if (relu) v = fmaxf(v, 0.0f);
            C[(size_t)r * N + c] = v;
        }
    }
}

// ---------------------------------------------------------------------------
// Attention scores + mask + softmax.
// qf, kf: flat [B*S, D]; head h occupies columns [h*DK, (h+1)*DK).
// attn out: [B, H, S, S].
// causal=0: mask is src_mask [B, S] (padding over keys).
// causal=1: mask is tgt_mask [B, S, S].
// Block: 8 query rows x all 512 keys; grid (S/8, B*H); 256 threads.
// ---------------------------------------------------------------------------
__global__ __launch_bounds__(256)
void attn_scores_kernel(const float* __restrict__ qf,
                        const float* __restrict__ kf,
                        const int* __restrict__ mask,
                        int causal,
                        float* __restrict__ attn)
{
    const int bh = blockIdx.y;
    const int b = bh >> 4, h = bh & 15;
    const int q0 = blockIdx.x * 8;
    const int t = threadIdx.x;

    __shared__ float qs[8][64];
    __shared__ float ks[64][65];
    __shared__ float sc[8][512];

#pragma unroll
    for (int i = 0; i < 2; i++) {
        int idx = t + i * 256;
        int qi = idx >> 6, d = idx & 63;
        qs[qi][d] = qf[(size_t)(b * SS + q0 + qi) * DD + h * DKK + d];
    }

    for (int kt = 0; kt < 8; kt++) {
        __syncthreads();
#pragma unroll
        for (int i = 0; i < 16; i++) {
            int idx = t + i * 256;
            int kk = idx >> 6, d = idx & 63;
            ks[kk][d] = kf[(size_t)(b * SS + kt * 64 + kk) * DD + h * DKK + d];
        }
        __syncthreads();
#pragma unroll
        for (int p = 0; p < 2; p++) {
            int pair = t + p * 256;
            int qi = pair >> 6, kj = pair & 63;
            float dot = 0.0f;
#pragma unroll
            for (int d = 0; d < 64; d++)
                dot = fmaf(qs[qi][d], ks[kj][d], dot);
            sc[qi][kt * 64 + kj] = dot;
        }
    }
    __syncthreads();

    // softmax: warp w owns row q0+w
    const int w = t >> 5, lane = t & 31;
    const int q = q0 + w;
    float vals[16];
    float mx = -1e30f;
#pragma unroll
    for (int i = 0; i < 16; i++) {
        int j = lane + i * 32;
        float v = sc[w][j] * INV_SCALE;
        int m = causal ? mask[((size_t)b * SS + q) * SS + j]
                       : mask[(size_t)b * SS + j];
        if (m == 0) v = -1e9f;
        vals[i] = v;
        mx = fmaxf(mx, v);
    }
#pragma unroll
    for (int o = 16; o > 0; o >>= 1)
        mx = fmaxf(mx, __shfl_xor_sync(0xffffffffu, mx, o));
    float sum = 0.0f;
#pragma unroll
    for (int i = 0; i < 16; i++) {
        vals[i] = expf(vals[i] - mx);
        sum += vals[i];
    }
#pragma unroll
    for (int o = 16; o > 0; o >>= 1)
        sum += __shfl_xor_sync(0xffffffffu, sum, o);
    float inv = 1.0f / sum;

    float* dst = attn + ((size_t)bh * SS + q) * SS;
#pragma unroll
    for (int i = 0; i < 16; i++)
        dst[lane + i * 32] = vals[i] * inv;
}

// ---------------------------------------------------------------------------
// Context: for each (b,h): ctx[q,d] = sum_k attn[q,k] * V[k,d]
// attn: [B,H,S,S]; vf flat [B*S, D] (head h at col h*DK); ctx flat [B*S, D].
// grid (S/64, B*H), 256 threads, tile 64q x 64d, K=S.
// ---------------------------------------------------------------------------
__global__ __launch_bounds__(256)
void attn_ctx_kernel(const float* __restrict__ attn,
                     const float* __restrict__ vf,
                     float* __restrict__ ctx)
{
    const int bh = blockIdx.y;
    const int b = bh >> 4, h = bh & 15;
    const int q0 = blockIdx.x * 64;
    const float* A = attn + (size_t)bh * SS * SS;
    const float* V = vf + (size_t)b * SS * DD + h * DKK;
    float* Cp = ctx + (size_t)b * SS * DD + h * DKK;

    const int t = threadIdx.x, tx = t & 15, ty = t >> 4;
    __shared__ float As[16][65];
    __shared__ float Bs[16][64];
    float acc[4][4] = {};

    for (int k0 = 0; k0 < SS; k0 += 16) {
#pragma unroll
        for (int i = 0; i < 4; i++) {
            int idx = t + i * 256;
            int ar = idx >> 4, ac = idx & 15;
            As[ac][ar] = A[(size_t)(q0 + ar) * SS + k0 + ac];
            int br = idx >> 6, bc = idx & 63;
            Bs[br][bc] = V[(size_t)(k0 + br) * DD + bc];
        }
        __syncthreads();
#pragma unroll
        for (int kk = 0; kk < 16; kk++) {
            float a[4], bv[4];
#pragma unroll
            for (int i = 0; i < 4; i++) a[i] = As[kk][ty * 4 + i];
#pragma unroll
            for (int j = 0; j < 4; j++) bv[j] = Bs[kk][tx * 4 + j];
#pragma unroll
            for (int i = 0; i < 4; i++)
#pragma unroll
                for (int j = 0; j < 4; j++)
                    acc[i][j] = fmaf(a[i], bv[j], acc[i][j]);
        }
        __syncthreads();
    }

#pragma unroll
    for (int i = 0; i < 4; i++)
#pragma unroll
        for (int j = 0; j < 4; j++)
            Cp[(size_t)(q0 + ty * 4 + i) * DD + tx * 4 + j] = acc[i][j];
}

// ---------------------------------------------------------------------------
// y = LayerNorm(x + a) with per-channel gamma/beta. a may be nullptr.
// One block per row (D=1024), 256 threads, 4 values/thread.
// In-place (y == x) is safe: all reads complete before the reduction barrier.
// ---------------------------------------------------------------------------
__global__ __launch_bounds__(256)
void add_ln_kernel(const float* __restrict__ x,
                   const float* __restrict__ a,
                   const float* __restrict__ g,
                   const float* __restrict__ bt,
                   float* __restrict__ y)
{
    const int row = blockIdx.x;
    const int t = threadIdx.x;
    __shared__ float red[256];

    float v[4];
#pragma unroll
    for (int i = 0; i < 4; i++) {
        int c = t + i * 256;
        float vv = x[(size_t)row * DD + c];
        if (a) vv += a[(size_t)row * DD + c];
        v[i] = vv;
    }
    float s = v[0] + v[1] + v[2] + v[3];
    red[t] = s;
    __syncthreads();
    for (int o = 128; o > 0; o >>= 1) {
        if (t < o) red[t] += red[t + o];
        __syncthreads();
    }
    float mean = red[0] * (1.0f / DD);
    __syncthreads();

    float s2 = 0.0f;
#pragma unroll
    for (int i = 0; i < 4; i++) {
        float d = v[i] - mean;
        s2 += d * d;
    }
    red[t] = s2;
    __syncthreads();
    for (int o = 128; o > 0; o >>= 1) {
        if (t < o) red[t] += red[t + o];
        __syncthreads();
    }
    float var = red[0] * (1.0f / DD);
    float inv = rsqrtf(var + EPSF);

#pragma unroll
    for (int i = 0; i < 4; i++) {
        int c = t + i * 256;
        y[(size_t)row * DD + c] = g[c] * (v[i] - mean) * inv + bt[c];
    }
}

// ---------------------------------------------------------------------------
// Host orchestration
// ---------------------------------------------------------------------------
extern "C" void kernel_launch(void* const* d_in, const int* in_sizes, int n_in,
                              void* d_out, int out_size)
{
    const float* src     = (const float*)d_in[0];
    const float* tgt     = (const float*)d_in[1];
    const float* enc_W   = (const float*)d_in[2];
    const float* enc_b   = (const float*)d_in[3];
    const float* enc_W1  = (const float*)d_in[4];
    const float* enc_b1  = (const float*)d_in[5];
    const float* enc_W2  = (const float*)d_in[6];
    const float* enc_b2  = (const float*)d_in[7];
    const float* enc_lng = (const float*)d_in[8];
    const float* enc_lnb = (const float*)d_in[9];
    const float* enc_fg  = (const float*)d_in[10];
    const float* enc_fb  = (const float*)d_in[11];
    const float* dsW     = (const float*)d_in[12];
    const float* dsb     = (const float*)d_in[13];
    const float* dcW     = (const float*)d_in[14];
    const float* dcb     = (const float*)d_in[15];
    const float* dW1     = (const float*)d_in[16];
    const float* db1     = (const float*)d_in[17];
    const float* dW2     = (const float*)d_in[18];
    const float* db2     = (const float*)d_in[19];
    const float* dlng    = (const float*)d_in[20];
    const float* dlnb    = (const float*)d_in[21];
    const float* dfg     = (const float*)d_in[22];
    const float* dfb     = (const float*)d_in[23];
    const int*   src_mask = (const int*)d_in[24];
    const int*   tgt_mask = (const int*)d_in[25];
    float* out = (float*)d_out;

    float* scratch = nullptr;
    cudaGetSymbolAddress((void**)&scratch, g_scratch);

    float* X   = scratch + 0 * MEG;
    float* X2  = scratch + 1 * MEG;
    float* Qb  = scratch + 2 * MEG;
    float* Kb  = scratch + 3 * MEG;
    float* Vb  = scratch + 4 * MEG;
    float* Ab  = scratch + 5 * MEG;
    float* H1  = scratch + 6 * MEG;   // 4M floats
    float* ATT = scratch + 10 * MEG;  // 8M floats
    float* ENC = scratch + 18 * MEG;

    const size_t SLAB      = (size_t)BB * HH * SS * SS;  // 8,388,608
    const size_t OFF_ENC   = (size_t)BB * SS * DD;       // 1,048,576
    const size_t OFF_SELF  = OFF_ENC + (size_t)LL * SLAB;
    const size_t OFF_CROSS = OFF_SELF + (size_t)LL * SLAB;
    const size_t TOTAL     = OFF_CROSS + (size_t)LL * SLAB;
    const bool full = ((size_t)out_size >= TOTAL);

    dim3 gD(DD / 64, MROWS / 64);     // projection GEMMs: 16x16 blocks
    dim3 gFF(DFFF / 64, MROWS / 64);  // FFN1: 64x16 blocks
    dim3 gS(SS / 8, BB * HH);         // scores: 64x32 blocks
    dim3 gC(SS / 64, BB * HH);        // ctx:    8x32 blocks

    // ------------------------- Encoder -------------------------
    const float* cur = src;
    for (int l = 0; l < LL; l++) {
        const float* W  = enc_W + (size_t)l * 4 * DD * DD;
        const float* bb = enc_b + (size_t)l * 4 * DD;
        gemm_bias_kernel<<<gD, 256>>>(cur, W,              bb,          Qb, MROWS, DD, DD, 0);
        gemm_bias_kernel<<<gD, 256>>>(cur, W + DD * DD,    bb + DD,     Kb, MROWS, DD, DD, 0);
        gemm_bias_kernel<<<gD, 256>>>(cur, W + 2 * DD * DD, bb + 2 * DD, Vb, MROWS, DD, DD, 0);
        float* adst = full ? out + OFF_ENC + (size_t)l * SLAB : ATT;
        attn_scores_kernel<<<gS, 256>>>(Qb, Kb, src_mask, 0, adst);
        attn_ctx_kernel<<<gC, 256>>>(adst, Vb, Qb);
        gemm_bias_kernel<<<gD, 256>>>(Qb, W + 3 * DD * DD, bb + 3 * DD, Ab, MROWS, DD, DD, 0);
        add_ln_kernel<<<MROWS, 256>>>(cur, Ab, enc_lng + (size_t)l * 2 * DD,
                                      enc_lnb + (size_t)l * 2 * DD, X2);
        gemm_bias_kernel<<<gFF, 256>>>(X2, enc_W1 + (size_t)l * DD * DFFF,
                                       enc_b1 + (size_t)l * DFFF, H1, MROWS, DFFF, DD, 1);
        gemm_bias_kernel<<<gD, 256>>>(H1, enc_W2 + (size_t)l * DFFF * DD,
                                      enc_b2 + (size_t)l * DD, Ab, MROWS, DD, DFFF, 0);
        add_ln_kernel<<<MROWS, 256>>>(X2, Ab, enc_lng + (size_t)l * 2 * DD + DD,
                                      enc_lnb + (size_t)l * 2 * DD + DD, X);
        cur = X;
    }
    add_ln_kernel<<<MROWS, 256>>>(cur, nullptr, enc_fg, enc_fb, ENC);

    // ------------------------- Decoder -------------------------
    cur = tgt;
    for (int l = 0; l < LL; l++) {
        // self-attention (causal)
        const float* Ws = dsW + (size_t)l * 4 * DD * DD;
        const float* bs = dsb + (size_t)l * 4 * DD;
        gemm_bias_kernel<<<gD, 256>>>(cur, Ws,               bs,          Qb, MROWS, DD, DD, 0);
        gemm_bias_kernel<<<gD, 256>>>(cur, Ws + DD * DD,     bs + DD,     Kb, MROWS, DD, DD, 0);
        gemm_bias_kernel<<<gD, 256>>>(cur, Ws + 2 * DD * DD, bs + 2 * DD, Vb, MROWS, DD, DD, 0);
        float* adst = full ? out + OFF_SELF + (size_t)l * SLAB : ATT;
        attn_scores_kernel<<<gS, 256>>>(Qb, Kb, tgt_mask, 1, adst);
        attn_ctx_kernel<<<gC, 256>>>(adst, Vb, Qb);
        gemm_bias_kernel<<<gD, 256>>>(Qb, Ws + 3 * DD * DD, bs + 3 * DD, Ab, MROWS, DD, DD, 0);
        add_ln_kernel<<<MROWS, 256>>>(cur, Ab, dlng + (size_t)l * 3 * DD,
                                      dlnb + (size_t)l * 3 * DD, X);

        // cross-attention (queries from X, keys/values from encoder output)
        const float* Wc = dcW + (size_t)l * 4 * DD * DD;
        const float* bc = dcb + (size_t)l * 4 * DD;
        gemm_bias_kernel<<<gD, 256>>>(X,   Wc,               bc,          Qb, MROWS, DD, DD, 0);
        gemm_bias_kernel<<<gD, 256>>>(ENC, Wc + DD * DD,     bc + DD,     Kb, MROWS, DD, DD, 0);
        gemm_bias_kernel<<<gD, 256>>>(ENC, Wc + 2 * DD * DD, bc + 2 * DD, Vb, MROWS, DD, DD, 0);
        adst = full ? out + OFF_CROSS + (size_t)l * SLAB : ATT;
        attn_scores_kernel<<<gS, 256>>>(Qb, Kb, src_mask, 0, adst);
        attn_ctx_kernel<<<gC, 256>>>(adst, Vb, Qb);
        gemm_bias_kernel<<<gD, 256>>>(Qb, Wc + 3 * DD * DD, bc + 3 * DD, Ab, MROWS, DD, DD, 0);
        add_ln_kernel<<<MROWS, 256>>>(X, Ab, dlng + (size_t)l * 3 * DD + DD,
                                      dlnb + (size_t)l * 3 * DD + DD, X2);

        // FFN
        gemm_bias_kernel<<<gFF, 256>>>(X2, dW1 + (size_t)l * DD * DFFF,
                                       db1 + (size_t)l * DFFF, H1, MROWS, DFFF, DD, 1);
        gemm_bias_kernel<<<gD, 256>>>(H1, dW2 + (size_t)l * DFFF * DD,
                                      db2 + (size_t)l * DD, Ab, MROWS, DD, DFFF, 0);
        add_ln_kernel<<<MROWS, 256>>>(X2, Ab, dlng + (size_t)l * 3 * DD + 2 * DD,
                                      dlnb + (size_t)l * 3 * DD + 2 * DD, X);
        cur = X;
    }
    add_ln_kernel<<<MROWS, 256>>>(cur, nullptr, dfg, dfb, out);
}

// round 2
// speedup vs baseline: 2.1794x; 2.1794x over previous
#include <cuda_runtime.h>
#include <cuda_bf16.h>
#include <cstdint>
#include <cstddef>

// ---------------------------------------------------------------------------
// Transformer forward (encoder-decoder), tf32 tensor-core version.
// B=2, S=512, D=1024, H=16, DK=64, DFF=4096, L=4.
// ---------------------------------------------------------------------------

#define BB   2
#define SS   512
#define DD   1024
#define HH   16
#define DKK  64
#define DFFF 4096
#define LL   4
#define MROWS (BB*SS)          // 1024
#define EPSF 1e-5f
#define INV_SCALE 0.125f       // 1/sqrt(DK)

static const size_t MEG = 1u << 20;
__device__ __align__(16) float g_scratch[19u * (1u << 20)];

// ---------------------------------------------------------------------------
// tf32 helpers
// ---------------------------------------------------------------------------
__device__ __forceinline__ uint32_t f2t(float x) {
    uint32_t r; asm("cvt.rna.tf32.f32 %0, %1;" : "=r"(r) : "f"(x)); return r;
}
__device__ __forceinline__ void mma8(float* c, const uint32_t* a, const uint32_t* b) {
    asm volatile(
        "mma.sync.aligned.m16n8k8.row.col.f32.tf32.tf32.f32 "
        "{%0,%1,%2,%3}, {%4,%5,%6,%7}, {%8,%9}, {%0,%1,%2,%3};\n"
        : "+f"(c[0]), "+f"(c[1]), "+f"(c[2]), "+f"(c[3])
        : "r"(a[0]), "r"(a[1]), "r"(a[2]), "r"(a[3]), "r"(b[0]), "r"(b[1]));
}
__device__ __forceinline__ uint4 cvt4(float4 v) {
    uint4 u; u.x = f2t(v.x); u.y = f2t(v.y); u.z = f2t(v.z); u.w = f2t(v.w);
    return u;
}

// ---------------------------------------------------------------------------
// tf32 GEMM: C[M, totalN] = A[M,K] @ W + bias, optional ReLU.
// W/bias/C may be "blocked" along N in chunks of nb (for fused QKV):
//   blk = col/nb; W base += blk*wstride; bias += blk*nb; C += blk*cstride;
//   inner row strides of W and C are nb.
// Block tile 128x128, 8 warps (each 64x32), K-step 16, reg-prefetch pipeline.
// ---------------------------------------------------------------------------
__global__ __launch_bounds__(256, 2)
void gemm_tf32(const float* __restrict__ A, const float* __restrict__ W,
               const float* __restrict__ bias, float* __restrict__ C,
               int M, int K, int nb, int relu,
               long long wstride, long long cstride)
{
    __shared__ uint32_t As[128 * 20];   // [m][k], stride 20
    __shared__ uint32_t Bs[16 * 136];   // [k][n], stride 136
    const int t = threadIdx.x;
    const int lane = t & 31, w = t >> 5;
    const int g = lane >> 2, cc = lane & 3;
    const int wm = w >> 2, wn = w & 3;          // warp tile: (wm*64, wn*32)
    const int row0 = blockIdx.y * 128;
    const int colg = blockIdx.x * 128;
    const int blk  = colg / nb;
    const int col0 = colg - blk * nb;
    const float* Wp = W + (size_t)blk * (size_t)wstride;
    const float* bp = bias + (size_t)blk * nb;
    float* Cp = C + (size_t)blk * (size_t)cstride;

    const int ar = t >> 2, ak = (t & 3) << 2;   // A-load coords
    const int bk = t >> 5, bc = (t & 31) << 2;  // B-load coords

    float4 aR0, aR1, bR0, bR1;
    aR0 = *(const float4*)&A[(size_t)(row0 + ar) * K + ak];
    aR1 = *(const float4*)&A[(size_t)(row0 + 64 + ar) * K + ak];
    bR0 = *(const float4*)&Wp[(size_t)bk * nb + col0 + bc];
    bR1 = *(const float4*)&Wp[(size_t)(bk + 8) * nb + col0 + bc];

    float acc[4][4][4] = {};
    uint32_t af[4][4], bf[4][2];

    for (int k0 = 0; k0 < K; k0 += 16) {
        *(uint4*)&As[ar * 20 + ak]        = cvt4(aR0);
        *(uint4*)&As[(64 + ar) * 20 + ak] = cvt4(aR1);
        *(uint4*)&Bs[bk * 136 + bc]       = cvt4(bR0);
        *(uint4*)&Bs[(bk + 8) * 136 + bc] = cvt4(bR1);
        __syncthreads();

        if (k0 + 16 < K) {
            aR0 = *(const float4*)&A[(size_t)(row0 + ar) * K + k0 + 16 + ak];
            aR1 = *(const float4*)&A[(size_t)(row0 + 64 + ar) * K + k0 + 16 + ak];
            bR0 = *(const float4*)&Wp[(size_t)(k0 + 16 + bk) * nb + col0 + bc];
            bR1 = *(const float4*)&Wp[(size_t)(k0 + 24 + bk) * nb + col0 + bc];
        }

#pragma unroll
        for (int ks = 0; ks < 2; ks++) {
            const int kb = ks * 8 + cc;
#pragma unroll
            for (int mi = 0; mi < 4; mi++) {
                const int mb = wm * 64 + mi * 16;
                af[mi][0] = As[(mb + g) * 20 + kb];
                af[mi][1] = As[(mb + g + 8) * 20 + kb];
                af[mi][2] = As[(mb + g) * 20 + kb + 4];
                af[mi][3] = As[(mb + g + 8) * 20 + kb + 4];
            }
#pragma unroll
            for (int nj = 0; nj < 4; nj++) {
                const int nbase = wn * 32 + nj * 8;
                bf[nj][0] = Bs[kb * 136 + nbase + g];
                bf[nj][1] = Bs[(kb + 4) * 136 + nbase + g];
            }
#pragma unroll
            for (int mi = 0; mi < 4; mi++)
#pragma unroll
                for (int nj = 0; nj < 4; nj++)
                    mma8(acc[mi][nj], af[mi], bf[nj]);
        }
        __syncthreads();
    }

#pragma unroll
    for (int mi = 0; mi < 4; mi++) {
        const int r0 = row0 + wm * 64 + mi * 16 + g;
#pragma unroll
        for (int nj = 0; nj < 4; nj++) {
            const int c = col0 + wn * 32 + nj * 8 + 2 * cc;
            const float b0v = bp[c], b1v = bp[c + 1];
            float v0 = acc[mi][nj][0] + b0v, v1 = acc[mi][nj][1] + b1v;
            float v2 = acc[mi][nj][2] + b0v, v3 = acc[mi][nj][3] + b1v;
            if (relu) {
                v0 = fmaxf(v0, 0.f); v1 = fmaxf(v1, 0.f);
                v2 = fmaxf(v2, 0.f); v3 = fmaxf(v3, 0.f);
            }
            *(float2*)&Cp[(size_t)r0 * nb + c]       = make_float2(v0, v1);
            *(float2*)&Cp[(size_t)(r0 + 8) * nb + c] = make_float2(v2, v3);
        }
    }
}

// ---------------------------------------------------------------------------
// Fused scores + mask + softmax (tf32 mma for Q.K^T, softmax in smem).
// Block: 64 q-rows x 512 keys; grid (S/64, B*H); 256 threads.
// Dynamic smem: Qs(64x68 u32) Ks(64x68 u32) S(64x516 f32) ~163 KB.
// ---------------------------------------------------------------------------
__global__ __launch_bounds__(256)
void attn_scores_tf32(const float* __restrict__ qf,
                      const float* __restrict__ kf,
                      const int* __restrict__ mask,
                      int causal,
                      float* __restrict__ attn)
{
    extern __shared__ float smemf[];
    uint32_t* Qs = (uint32_t*)smemf;        // 64*68
    uint32_t* Ks = Qs + 64 * 68;            // 64*68
    float* Ssm = smemf + 2 * 64 * 68;       // 64*516

    const int bh = blockIdx.y, b = bh >> 4, h = bh & 15;
    const int q0 = blockIdx.x * 64;
    const int t = threadIdx.x, lane = t & 31, w = t >> 5;
    const int g = lane >> 2, cc = lane & 3;
    const int qslot = w & 3, kslot = w >> 2;   // 4 x 2 warp grid, warp tile 16x32

    // Load Q tile 64x64 (tf32)
#pragma unroll
    for (int i = 0; i < 4; i++) {
        const int idx = t + i * 256;
        const int r = idx >> 4, cq = (idx & 15) << 2;
        float4 v = *(const float4*)&qf[(size_t)(b * SS + q0 + r) * DD + h * DKK + cq];
        *(uint4*)&Qs[r * 68 + cq] = cvt4(v);
    }

    for (int kt = 0; kt < 8; kt++) {
        __syncthreads();
#pragma unroll
        for (int i = 0; i < 4; i++) {
            const int idx = t + i * 256;
            const int r = idx >> 4, cq = (idx & 15) << 2;
            float4 v = *(const float4*)&kf[(size_t)(b * SS + kt * 64 + r) * DD + h * DKK + cq];
            *(uint4*)&Ks[r * 68 + cq] = cvt4(v);
        }
        __syncthreads();

        float acc[4][4] = {};
        uint32_t af[4];
#pragma unroll
        for (int ks = 0; ks < 8; ks++) {
            const int kb = ks * 8 + cc;
            const int mb = qslot * 16;
            af[0] = Qs[(mb + g) * 68 + kb];
            af[1] = Qs[(mb + g + 8) * 68 + kb];
            af[2] = Qs[(mb + g) * 68 + kb + 4];
            af[3] = Qs[(mb + g + 8) * 68 + kb + 4];
#pragma unroll
            for (int nj = 0; nj < 4; nj++) {
                const int nbase = kslot * 32 + nj * 8;
                uint32_t bf[2];
                bf[0] = Ks[(nbase + g) * 68 + kb];
                bf[1] = Ks[(nbase + g) * 68 + kb + 4];
                mma8(acc[nj], af, bf);
            }
        }
#pragma unroll
        for (int nj = 0; nj < 4; nj++) {
            const int colb = kt * 64 + kslot * 32 + nj * 8 + 2 * cc;
            const int rr = qslot * 16 + g;
            *(float2*)&Ssm[rr * 516 + colb]       = make_float2(acc[nj][0], acc[nj][1]);
            *(float2*)&Ssm[(rr + 8) * 516 + colb] = make_float2(acc[nj][2], acc[nj][3]);
        }
    }
    __syncthreads();

    // Softmax: warp w handles rows w*8 .. w*8+7
    for (int i = 0; i < 8; i++) {
        const int rloc = w * 8 + i;
        const int q = q0 + rloc;
        float vals[16];
        float mx = -1e30f;
#pragma unroll
        for (int j = 0; j < 16; j++) {
            const int col = lane + j * 32;
            float v = Ssm[rloc * 516 + col] * INV_SCALE;
            const int m = causal ? mask[((size_t)b * SS + q) * SS + col]
                                 : mask[(size_t)b * SS + col];
            if (m == 0) v = -1e9f;
            vals[j] = v;
            mx = fmaxf(mx, v);
        }
#pragma unroll
        for (int o = 16; o > 0; o >>= 1)
            mx = fmaxf(mx, __shfl_xor_sync(0xffffffffu, mx, o));
        float sum = 0.0f;
#pragma unroll
        for (int j = 0; j < 16; j++) {
            vals[j] = expf(vals[j] - mx);
            sum += vals[j];
        }
#pragma unroll
        for (int o = 16; o > 0; o >>= 1)
            sum += __shfl_xor_sync(0xffffffffu, sum, o);
        const float inv = 1.0f / sum;
        float* dst = attn + ((size_t)bh * SS + q) * SS;
#pragma unroll
        for (int j = 0; j < 16; j++)
            dst[lane + j * 32] = vals[j] * inv;
    }
}

// ---------------------------------------------------------------------------
// Context: ctx[q,d] = sum_k attn[q,k] * V[k,d], tf32 mma.
// Block 64q x 64d per (bh, qtile); grid (S/64, B*H); 256 threads.
// ---------------------------------------------------------------------------
__global__ __launch_bounds__(256)
void attn_ctx_tf32(const float* __restrict__ attn,
                   const float* __restrict__ vf,
                   float* __restrict__ ctx)
{
    __shared__ uint32_t As[64 * 20];   // [q][k], stride 20
    __shared__ uint32_t Vs[16 * 72];   // [k][d], stride 72
    const int bh = blockIdx.y, b = bh >> 4, h = bh & 15;
    const int q0 = blockIdx.x * 64;
    const int t = threadIdx.x, lane = t & 31, w = t >> 5;
    const int g = lane >> 2, cc = lane & 3;
    const int qslot = w & 3, dslot = w >> 2;
    const float* Ap = attn + (size_t)bh * SS * SS;
    const float* Vp = vf + (size_t)b * SS * DD + h * DKK;

    float acc[4][4] = {};
    for (int k0 = 0; k0 < SS; k0 += 16) {
        {
            const int r = t >> 2, ak = (t & 3) << 2;
            float4 v = *(const float4*)&Ap[(size_t)(q0 + r) * SS + k0 + ak];
            *(uint4*)&As[r * 20 + ak] = cvt4(v);
        }
        {
            const int kr = t >> 4, cq = (t & 15) << 2;
            float4 v = *(const float4*)&Vp[(size_t)(k0 + kr) * DD + cq];
            *(uint4*)&Vs[kr * 72 + cq] = cvt4(v);
        }
        __syncthreads();

        uint32_t af[4], bf[2];
#pragma unroll
        for (int ks = 0; ks < 2; ks++) {
            const int kb = ks * 8 + cc;
            const int mb = qslot * 16;
            af[0] = As[(mb + g) * 20 + kb];
            af[1] = As[(mb + g + 8) * 20 + kb];
            af[2] = As[(mb + g) * 20 + kb + 4];
            af[3] = As[(mb + g + 8) * 20 + kb + 4];
#pragma unroll
            for (int nj = 0; nj < 4; nj++) {
                const int nbase = dslot * 32 + nj * 8;
                bf[0] = Vs[kb * 72 + nbase + g];
                bf[1] = Vs[(kb + 4) * 72 + nbase + g];
                mma8(acc[nj], af, bf);
            }
        }
        __syncthreads();
    }

    float* Cp = ctx + (size_t)b * SS * DD + h * DKK;
#pragma unroll
    for (int nj = 0; nj < 4; nj++) {
        const int c = dslot * 32 + nj * 8 + 2 * cc;
        const int r = q0 + qslot * 16 + g;
        *(float2*)&Cp[(size_t)r * DD + c]       = make_float2(acc[nj][0], acc[nj][1]);
        *(float2*)&Cp[(size_t)(r + 8) * DD + c] = make_float2(acc[nj][2], acc[nj][3]);
    }
}

// ---------------------------------------------------------------------------
// y = LayerNorm(x + a). a may be nullptr. One block per row (D=1024).
// ---------------------------------------------------------------------------
__global__ __launch_bounds__(256)
void add_ln_kernel(const float* __restrict__ x,
                   const float* __restrict__ a,
                   const float* __restrict__ g,
                   const float* __restrict__ bt,
                   float* __restrict__ y)
{
    const int row = blockIdx.x;
    const int t = threadIdx.x;
    __shared__ float red[256];

    float v[4];
#pragma unroll
    for (int i = 0; i < 4; i++) {
        const int c = t + i * 256;
        float vv = x[(size_t)row * DD + c];
        if (a) vv += a[(size_t)row * DD + c];
        v[i] = vv;
    }
    float s = v[0] + v[1] + v[2] + v[3];
    red[t] = s;
    __syncthreads();
    for (int o = 128; o > 0; o >>= 1) {
        if (t < o) red[t] += red[t + o];
        __syncthreads();
    }
    const float mean = red[0] * (1.0f / DD);
    __syncthreads();

    float s2 = 0.0f;
#pragma unroll
    for (int i = 0; i < 4; i++) {
        const float d = v[i] - mean;
        s2 += d * d;
    }
    red[t] = s2;
    __syncthreads();
    for (int o = 128; o > 0; o >>= 1) {
        if (t < o) red[t] += red[t + o];
        __syncthreads();
    }
    const float var = red[0] * (1.0f / DD);
    const float inv = rsqrtf(var + EPSF);

#pragma unroll
    for (int i = 0; i < 4; i++) {
        const int c = t + i * 256;
        y[(size_t)row * DD + c] = g[c] * (v[i] - mean) * inv + bt[c];
    }
}

// ---------------------------------------------------------------------------
// Host orchestration
// ---------------------------------------------------------------------------
extern "C" void kernel_launch(void* const* d_in, const int* in_sizes, int n_in,
                              void* d_out, int out_size)
{
    const float* src     = (const float*)d_in[0];
    const float* tgt     = (const float*)d_in[1];
    const float* enc_W   = (const float*)d_in[2];
    const float* enc_b   = (const float*)d_in[3];
    const float* enc_W1  = (const float*)d_in[4];
    const float* enc_b1  = (const float*)d_in[5];
    const float* enc_W2  = (const float*)d_in[6];
    const float* enc_b2  = (const float*)d_in[7];
    const float* enc_lng = (const float*)d_in[8];
    const float* enc_lnb = (const float*)d_in[9];
    const float* enc_fg  = (const float*)d_in[10];
    const float* enc_fb  = (const float*)d_in[11];
    const float* dsW     = (const float*)d_in[12];
    const float* dsb     = (const float*)d_in[13];
    const float* dcW     = (const float*)d_in[14];
    const float* dcb     = (const float*)d_in[15];
    const float* dW1     = (const float*)d_in[16];
    const float* db1     = (const float*)d_in[17];
    const float* dW2     = (const float*)d_in[18];
    const float* db2     = (const float*)d_in[19];
    const float* dlng    = (const float*)d_in[20];
    const float* dlnb    = (const float*)d_in[21];
    const float* dfg     = (const float*)d_in[22];
    const float* dfb     = (const float*)d_in[23];
    const int*   src_mask = (const int*)d_in[24];
    const int*   tgt_mask = (const int*)d_in[25];
    float* out = (float*)d_out;

    float* scratch = nullptr;
    cudaGetSymbolAddress((void**)&scratch, g_scratch);

    float* X   = scratch + 0 * MEG;
    float* X2  = scratch + 1 * MEG;
    float* Qb  = scratch + 2 * MEG;  // Q/K/V contiguous for fused QKV gemm
    float* Kb  = scratch + 3 * MEG;
    float* Vb  = scratch + 4 * MEG;
    float* Ab  = scratch + 5 * MEG;
    float* H1  = scratch + 6 * MEG;   // 4M floats
    float* ATT = scratch + 10 * MEG;  // 8M floats
    float* ENC = scratch + 18 * MEG;

    const size_t SLAB      = (size_t)BB * HH * SS * SS;
    const size_t OFF_ENC   = (size_t)BB * SS * DD;
    const size_t OFF_SELF  = OFF_ENC + (size_t)LL * SLAB;
    const size_t OFF_CROSS = OFF_SELF + (size_t)LL * SLAB;
    const size_t TOTAL     = OFF_CROSS + (size_t)LL * SLAB;
    const bool full = ((size_t)out_size >= TOTAL);

    const size_t SC_SMEM = (size_t)(2 * 64 * 68 + 64 * 516) * sizeof(float);
    cudaFuncSetAttribute(attn_scores_tf32,
                         cudaFuncAttributeMaxDynamicSharedMemorySize, (int)SC_SMEM);

    dim3 gQKV(3072 / 128, MROWS / 128);  // fused Q,K,V
    dim3 gKV(2048 / 128, MROWS / 128);   // fused K,V (cross)
    dim3 gO(DD / 128, MROWS / 128);      // DxD
    dim3 gF1(DFFF / 128, MROWS / 128);
    dim3 gS(SS / 64, BB * HH);
    dim3 gC(SS / 64, BB * HH);
    const long long WS = (long long)DD * DD;
    const long long CS = (long long)MEG;

    // ------------------------- Encoder -------------------------
    const float* cur = src;
    for (int l = 0; l < LL; l++) {
        const float* W  = enc_W + (size_t)l * 4 * DD * DD;
        const float* bb = enc_b + (size_t)l * 4 * DD;
        gemm_tf32<<<gQKV, 256>>>(cur, W, bb, Qb, MROWS, DD, DD, 0, WS, CS);
        float* adst = full ? out + OFF_ENC + (size_t)l * SLAB : ATT;
        attn_scores_tf32<<<gS, 256, SC_SMEM>>>(Qb, Kb, src_mask, 0, adst);
        attn_ctx_tf32<<<gC, 256>>>(adst, Vb, Qb);
        gemm_tf32<<<gO, 256>>>(Qb, W + 3 * DD * DD, bb + 3 * DD, Ab, MROWS, DD, DD, 0, 0, 0);
        add_ln_kernel<<<MROWS, 256>>>(cur, Ab, enc_lng + (size_t)l * 2 * DD,
                                      enc_lnb + (size_t)l * 2 * DD, X2);
        gemm_tf32<<<gF1, 256>>>(X2, enc_W1 + (size_t)l * DD * DFFF,
                                enc_b1 + (size_t)l * DFFF, H1, MROWS, DD, DFFF, 1, 0, 0);
        gemm_tf32<<<gO, 256>>>(H1, enc_W2 + (size_t)l * DFFF * DD,
                               enc_b2 + (size_t)l * DD, Ab, MROWS, DFFF, DD, 0, 0, 0);
        add_ln_kernel<<<MROWS, 256>>>(X2, Ab, enc_lng + (size_t)l * 2 * DD + DD,
                                      enc_lnb + (size_t)l * 2 * DD + DD, X);
        cur = X;
    }
    add_ln_kernel<<<MROWS, 256>>>(cur, nullptr, enc_fg, enc_fb, ENC);

    // ------------------------- Decoder -------------------------
    cur = tgt;
    for (int l = 0; l < LL; l++) {
        // self-attention (causal)
        const float* Ws = dsW + (size_t)l * 4 * DD * DD;
        const float* bs = dsb + (size_t)l * 4 * DD;
        gemm_tf32<<<gQKV, 256>>>(cur, Ws, bs, Qb, MROWS, DD, DD, 0, WS, CS);
        float* adst = full ? out + OFF_SELF + (size_t)l * SLAB : ATT;
        attn_scores_tf32<<<gS, 256, SC_SMEM>>>(Qb, Kb, tgt_mask, 1, adst);
        attn_ctx_tf32<<<gC, 256>>>(adst, Vb, Qb);
        gemm_tf32<<<gO, 256>>>(Qb, Ws + 3 * DD * DD, bs + 3 * DD, Ab, MROWS, DD, DD, 0, 0, 0);
        add_ln_kernel<<<MROWS, 256>>>(cur, Ab, dlng + (size_t)l * 3 * DD,
                                      dlnb + (size_t)l * 3 * DD, X);

        // cross-attention
        const float* Wc = dcW + (size_t)l * 4 * DD * DD;
        const float* bc = dcb + (size_t)l * 4 * DD;
        gemm_tf32<<<gO, 256>>>(X, Wc, bc, Qb, MROWS, DD, DD, 0, 0, 0);
        gemm_tf32<<<gKV, 256>>>(ENC, Wc + DD * DD, bc + DD, Kb, MROWS, DD, DD, 0, WS, CS);
        adst = full ? out + OFF_CROSS + (size_t)l * SLAB : ATT;
        attn_scores_tf32<<<gS, 256, SC_SMEM>>>(Qb, Kb, src_mask, 0, adst);
        attn_ctx_tf32<<<gC, 256>>>(adst, Vb, Qb);
        gemm_tf32<<<gO, 256>>>(Qb, Wc + 3 * DD * DD, bc + 3 * DD, Ab, MROWS, DD, DD, 0, 0, 0);
        add_ln_kernel<<<MROWS, 256>>>(X, Ab, dlng + (size_t)l * 3 * DD + DD,
                                      dlnb + (size_t)l * 3 * DD + DD, X2);

        // FFN
        gemm_tf32<<<gF1, 256>>>(X2, dW1 + (size_t)l * DD * DFFF,
                                db1 + (size_t)l * DFFF, H1, MROWS, DD, DFFF, 1, 0, 0);
        gemm_tf32<<<gO, 256>>>(H1, dW2 + (size_t)l * DFFF * DD,
                               db2 + (size_t)l * DD, Ab, MROWS, DFFF, DD, 0, 0, 0);
        add_ln_kernel<<<MROWS, 256>>>(X2, Ab, dlng + (size_t)l * 3 * DD + 2 * DD,
                                      dlnb + (size_t)l * 3 * DD + 2 * DD, X);
        cur = X;
    }
    add_ln_kernel<<<MROWS, 256>>>(cur, nullptr, dfg, dfb, out);
}

// round 3
// speedup vs baseline: 2.4139x; 1.1076x over previous
#include <cuda_runtime.h>
#include <cuda_bf16.h>
#include <cstdint>
#include <cstddef>

// ---------------------------------------------------------------------------
// Transformer forward (encoder-decoder), tf32 tensor-core version, R3:
// 64x128 GEMM tiles for full-chip coverage on DxD GEMMs.
// B=2, S=512, D=1024, H=16, DK=64, DFF=4096, L=4.
// ---------------------------------------------------------------------------

#define BB   2
#define SS   512
#define DD   1024
#define HH   16
#define DKK  64
#define DFFF 4096
#define LL   4
#define MROWS (BB*SS)          // 1024
#define EPSF 1e-5f
#define INV_SCALE 0.125f       // 1/sqrt(DK)

static const size_t MEG = 1u << 20;
__device__ __align__(16) float g_scratch[19u * (1u << 20)];

// ---------------------------------------------------------------------------
// tf32 helpers
// ---------------------------------------------------------------------------
__device__ __forceinline__ uint32_t f2t(float x) {
    uint32_t r; asm("cvt.rna.tf32.f32 %0, %1;" : "=r"(r) : "f"(x)); return r;
}
__device__ __forceinline__ void mma8(float* c, const uint32_t* a, const uint32_t* b) {
    asm volatile(
        "mma.sync.aligned.m16n8k8.row.col.f32.tf32.tf32.f32 "
        "{%0,%1,%2,%3}, {%4,%5,%6,%7}, {%8,%9}, {%0,%1,%2,%3};\n"
        : "+f"(c[0]), "+f"(c[1]), "+f"(c[2]), "+f"(c[3])
        : "r"(a[0]), "r"(a[1]), "r"(a[2]), "r"(a[3]), "r"(b[0]), "r"(b[1]));
}
__device__ __forceinline__ uint4 cvt4(float4 v) {
    uint4 u; u.x = f2t(v.x); u.y = f2t(v.y); u.z = f2t(v.z); u.w = f2t(v.w);
    return u;
}

// ---------------------------------------------------------------------------
// tf32 GEMM: C[M, totalN] = A[M,K] @ W + bias, optional ReLU.
// W/bias/C may be "blocked" along N in chunks of nb (for fused QKV):
//   blk = colg/nb; W base += blk*wstride; bias += blk*nb; C += blk*cstride;
//   inner row strides of W and C are nb.
// Block tile 64x128, 8 warps (each 32x32), K-step 16, reg-prefetch pipeline.
// Grid: (totalN/128, M/64).
// ---------------------------------------------------------------------------
__global__ __launch_bounds__(256, 2)
void gemm_tf32(const float* __restrict__ A, const float* __restrict__ W,
               const float* __restrict__ bias, float* __restrict__ C,
               int M, int K, int nb, int relu,
               long long wstride, long long cstride)
{
    __shared__ uint32_t As[64 * 20];    // [m][k], stride 20
    __shared__ uint32_t Bs[16 * 136];   // [k][n], stride 136
    const int t = threadIdx.x;
    const int lane = t & 31, w = t >> 5;
    const int g = lane >> 2, cc = lane & 3;
    const int wm = w >> 2, wn = w & 3;          // warp tile: (wm*32, wn*32)
    const int row0 = blockIdx.y * 64;
    const int colg = blockIdx.x * 128;
    const int blk  = colg / nb;
    const int col0 = colg - blk * nb;
    const float* Wp = W + (size_t)blk * (size_t)wstride;
    const float* bp = bias + (size_t)blk * nb;
    float* Cp = C + (size_t)blk * (size_t)cstride;

    const int ar = t >> 2, ak = (t & 3) << 2;   // A tile 64x16: 1 float4/thread
    const int bk = t >> 5, bc = (t & 31) << 2;  // B tile 16x128: 2 float4/thread

    float4 aR0, bR0, bR1;
    aR0 = *(const float4*)&A[(size_t)(row0 + ar) * K + ak];
    bR0 = *(const float4*)&Wp[(size_t)bk * nb + col0 + bc];
    bR1 = *(const float4*)&Wp[(size_t)(bk + 8) * nb + col0 + bc];

    float acc[2][4][4] = {};
    uint32_t af[2][4], bf[4][2];

    for (int k0 = 0; k0 < K; k0 += 16) {
        *(uint4*)&As[ar * 20 + ak]        = cvt4(aR0);
        *(uint4*)&Bs[bk * 136 + bc]       = cvt4(bR0);
        *(uint4*)&Bs[(bk + 8) * 136 + bc] = cvt4(bR1);
        __syncthreads();

        if (k0 + 16 < K) {
            aR0 = *(const float4*)&A[(size_t)(row0 + ar) * K + k0 + 16 + ak];
            bR0 = *(const float4*)&Wp[(size_t)(k0 + 16 + bk) * nb + col0 + bc];
            bR1 = *(const float4*)&Wp[(size_t)(k0 + 24 + bk) * nb + col0 + bc];
        }

#pragma unroll
        for (int ks = 0; ks < 2; ks++) {
            const int kb = ks * 8 + cc;
#pragma unroll
            for (int mi = 0; mi < 2; mi++) {
                const int mb = wm * 32 + mi * 16;
                af[mi][0] = As[(mb + g) * 20 + kb];
                af[mi][1] = As[(mb + g + 8) * 20 + kb];
                af[mi][2] = As[(mb + g) * 20 + kb + 4];
                af[mi][3] = As[(mb + g + 8) * 20 + kb + 4];
            }
#pragma unroll
            for (int nj = 0; nj < 4; nj++) {
                const int nbase = wn * 32 + nj * 8;
                bf[nj][0] = Bs[kb * 136 + nbase + g];
                bf[nj][1] = Bs[(kb + 4) * 136 + nbase + g];
            }
#pragma unroll
            for (int mi = 0; mi < 2; mi++)
#pragma unroll
                for (int nj = 0; nj < 4; nj++)
                    mma8(acc[mi][nj], af[mi], bf[nj]);
        }
        __syncthreads();
    }

#pragma unroll
    for (int mi = 0; mi < 2; mi++) {
        const int r0 = row0 + wm * 32 + mi * 16 + g;
#pragma unroll
        for (int nj = 0; nj < 4; nj++) {
            const int c = col0 + wn * 32 + nj * 8 + 2 * cc;
            const float b0v = bp[c], b1v = bp[c + 1];
            float v0 = acc[mi][nj][0] + b0v, v1 = acc[mi][nj][1] + b1v;
            float v2 = acc[mi][nj][2] + b0v, v3 = acc[mi][nj][3] + b1v;
            if (relu) {
                v0 = fmaxf(v0, 0.f); v1 = fmaxf(v1, 0.f);
                v2 = fmaxf(v2, 0.f); v3 = fmaxf(v3, 0.f);
            }
            *(float2*)&Cp[(size_t)r0 * nb + c]       = make_float2(v0, v1);
            *(float2*)&Cp[(size_t)(r0 + 8) * nb + c] = make_float2(v2, v3);
        }
    }
}

// ---------------------------------------------------------------------------
// Fused scores + mask + softmax (tf32 mma for Q.K^T, softmax in smem).
// Block: 64 q-rows x 512 keys; grid (S/64, B*H); 256 threads.
// Dynamic smem: Qs(64x68 u32) Ks(64x68 u32) S(64x516 f32) ~163 KB.
// ---------------------------------------------------------------------------
__global__ __launch_bounds__(256)
void attn_scores_tf32(const float* __restrict__ qf,
                      const float* __restrict__ kf,
                      const int* __restrict__ mask,
                      int causal,
                      float* __restrict__ attn)
{
    extern __shared__ float smemf[];
    uint32_t* Qs = (uint32_t*)smemf;        // 64*68
    uint32_t* Ks = Qs + 64 * 68;            // 64*68
    float* Ssm = smemf + 2 * 64 * 68;       // 64*516

    const int bh = blockIdx.y, b = bh >> 4, h = bh & 15;
    const int q0 = blockIdx.x * 64;
    const int t = threadIdx.x, lane = t & 31, w = t >> 5;
    const int g = lane >> 2, cc = lane & 3;
    const int qslot = w & 3, kslot = w >> 2;   // 4 x 2 warp grid, warp tile 16x32

    // Load Q tile 64x64 (tf32)
#pragma unroll
    for (int i = 0; i < 4; i++) {
        const int idx = t + i * 256;
        const int r = idx >> 4, cq = (idx & 15) << 2;
        float4 v = *(const float4*)&qf[(size_t)(b * SS + q0 + r) * DD + h * DKK + cq];
        *(uint4*)&Qs[r * 68 + cq] = cvt4(v);
    }

    for (int kt = 0; kt < 8; kt++) {
        __syncthreads();
#pragma unroll
        for (int i = 0; i < 4; i++) {
            const int idx = t + i * 256;
            const int r = idx >> 4, cq = (idx & 15) << 2;
            float4 v = *(const float4*)&kf[(size_t)(b * SS + kt * 64 + r) * DD + h * DKK + cq];
            *(uint4*)&Ks[r * 68 + cq] = cvt4(v);
        }
        __syncthreads();

        float acc[4][4] = {};
        uint32_t af[4];
#pragma unroll
        for (int ks = 0; ks < 8; ks++) {
            const int kb = ks * 8 + cc;
            const int mb = qslot * 16;
            af[0] = Qs[(mb + g) * 68 + kb];
            af[1] = Qs[(mb + g + 8) * 68 + kb];
            af[2] = Qs[(mb + g) * 68 + kb + 4];
            af[3] = Qs[(mb + g + 8) * 68 + kb + 4];
#pragma unroll
            for (int nj = 0; nj < 4; nj++) {
                const int nbase = kslot * 32 + nj * 8;
                uint32_t bf[2];
                bf[0] = Ks[(nbase + g) * 68 + kb];
                bf[1] = Ks[(nbase + g) * 68 + kb + 4];
                mma8(acc[nj], af, bf);
            }
        }
#pragma unroll
        for (int nj = 0; nj < 4; nj++) {
            const int colb = kt * 64 + kslot * 32 + nj * 8 + 2 * cc;
            const int rr = qslot * 16 + g;
            *(float2*)&Ssm[rr * 516 + colb]       = make_float2(acc[nj][0], acc[nj][1]);
            *(float2*)&Ssm[(rr + 8) * 516 + colb] = make_float2(acc[nj][2], acc[nj][3]);
        }
    }
    __syncthreads();

    // Softmax: warp w handles rows w*8 .. w*8+7
    for (int i = 0; i < 8; i++) {
        const int rloc = w * 8 + i;
        const int q = q0 + rloc;
        float vals[16];
        float mx = -1e30f;
#pragma unroll
        for (int j = 0; j < 16; j++) {
            const int col = lane + j * 32;
            float v = Ssm[rloc * 516 + col] * INV_SCALE;
            const int m = causal ? mask[((size_t)b * SS + q) * SS + col]
                                 : mask[(size_t)b * SS + col];
            if (m == 0) v = -1e9f;
            vals[j] = v;
            mx = fmaxf(mx, v);
        }
#pragma unroll
        for (int o = 16; o > 0; o >>= 1)
            mx = fmaxf(mx, __shfl_xor_sync(0xffffffffu, mx, o));
        float sum = 0.0f;
#pragma unroll
        for (int j = 0; j < 16; j++) {
            vals[j] = expf(vals[j] - mx);
            sum += vals[j];
        }
#pragma unroll
        for (int o = 16; o > 0; o >>= 1)
            sum += __shfl_xor_sync(0xffffffffu, sum, o);
        const float inv = 1.0f / sum;
        float* dst = attn + ((size_t)bh * SS + q) * SS;
#pragma unroll
        for (int j = 0; j < 16; j++)
            dst[lane + j * 32] = vals[j] * inv;
    }
}

// ---------------------------------------------------------------------------
// Context: ctx[q,d] = sum_k attn[q,k] * V[k,d], tf32 mma.
// Block 64q x 64d per (bh, qtile); grid (S/64, B*H); 256 threads.
// ---------------------------------------------------------------------------
__global__ __launch_bounds__(256)
void attn_ctx_tf32(const float* __restrict__ attn,
                   const float* __restrict__ vf,
                   float* __restrict__ ctx)
{
    __shared__ uint32_t As[64 * 20];   // [q][k], stride 20
    __shared__ uint32_t Vs[16 * 72];   // [k][d], stride 72
    const int bh = blockIdx.y, b = bh >> 4, h = bh & 15;
    const int q0 = blockIdx.x * 64;
    const int t = threadIdx.x, lane = t & 31, w = t >> 5;
    const int g = lane >> 2, cc = lane & 3;
    const int qslot = w & 3, dslot = w >> 2;
    const float* Ap = attn + (size_t)bh * SS * SS;
    const float* Vp = vf + (size_t)b * SS * DD + h * DKK;

    float acc[4][4] = {};
    for (int k0 = 0; k0 < SS; k0 += 16) {
        {
            const int r = t >> 2, ak = (t & 3) << 2;
            float4 v = *(const float4*)&Ap[(size_t)(q0 + r) * SS + k0 + ak];
            *(uint4*)&As[r * 20 + ak] = cvt4(v);
        }
        {
            const int kr = t >> 4, cq = (t & 15) << 2;
            float4 v = *(const float4*)&Vp[(size_t)(k0 + kr) * DD + cq];
            *(uint4*)&Vs[kr * 72 + cq] = cvt4(v);
        }
        __syncthreads();

        uint32_t af[4], bf[2];
#pragma unroll
        for (int ks = 0; ks < 2; ks++) {
            const int kb = ks * 8 + cc;
            const int mb = qslot * 16;
            af[0] = As[(mb + g) * 20 + kb];
            af[1] = As[(mb + g + 8) * 20 + kb];
            af[2] = As[(mb + g) * 20 + kb + 4];
            af[3] = As[(mb + g + 8) * 20 + kb + 4];
#pragma unroll
            for (int nj = 0; nj < 4; nj++) {
                const int nbase = dslot * 32 + nj * 8;
                bf[0] = Vs[kb * 72 + nbase + g];
                bf[1] = Vs[(kb + 4) * 72 + nbase + g];
                mma8(acc[nj], af, bf);
            }
        }
        __syncthreads();
    }

    float* Cp = ctx + (size_t)b * SS * DD + h * DKK;
#pragma unroll
    for (int nj = 0; nj < 4; nj++) {
        const int c = dslot * 32 + nj * 8 + 2 * cc;
        const int r = q0 + qslot * 16 + g;
        *(float2*)&Cp[(size_t)r * DD + c]       = make_float2(acc[nj][0], acc[nj][1]);
        *(float2*)&Cp[(size_t)(r + 8) * DD + c] = make_float2(acc[nj][2], acc[nj][3]);
    }
}

// ---------------------------------------------------------------------------
// y = LayerNorm(x + a). a may be nullptr. One block per row (D=1024).
// ---------------------------------------------------------------------------
__global__ __launch_bounds__(256)
void add_ln_kernel(const float* __restrict__ x,
                   const float* __restrict__ a,
                   const float* __restrict__ g,
                   const float* __restrict__ bt,
                   float* __restrict__ y)
{
    const int row = blockIdx.x;
    const int t = threadIdx.x;
    __shared__ float red[256];

    float v[4];
#pragma unroll
    for (int i = 0; i < 4; i++) {
        const int c = t + i * 256;
        float vv = x[(size_t)row * DD + c];
        if (a) vv += a[(size_t)row * DD + c];
        v[i] = vv;
    }
    float s = v[0] + v[1] + v[2] + v[3];
    red[t] = s;
    __syncthreads();
    for (int o = 128; o > 0; o >>= 1) {
        if (t < o) red[t] += red[t + o];
        __syncthreads();
    }
    const float mean = red[0] * (1.0f / DD);
    __syncthreads();

    float s2 = 0.0f;
#pragma unroll
    for (int i = 0; i < 4; i++) {
        const float d = v[i] - mean;
        s2 += d * d;
    }
    red[t] = s2;
    __syncthreads();
    for (int o = 128; o > 0; o >>= 1) {
        if (t < o) red[t] += red[t + o];
        __syncthreads();
    }
    const float var = red[0] * (1.0f / DD);
    const float inv = rsqrtf(var + EPSF);

#pragma unroll
    for (int i = 0; i < 4; i++) {
        const int c = t + i * 256;
        y[(size_t)row * DD + c] = g[c] * (v[i] - mean) * inv + bt[c];
    }
}

// ---------------------------------------------------------------------------
// Host orchestration
// ---------------------------------------------------------------------------
extern "C" void kernel_launch(void* const* d_in, const int* in_sizes, int n_in,
                              void* d_out, int out_size)
{
    const float* src     = (const float*)d_in[0];
    const float* tgt     = (const float*)d_in[1];
    const float* enc_W   = (const float*)d_in[2];
    const float* enc_b   = (const float*)d_in[3];
    const float* enc_W1  = (const float*)d_in[4];
    const float* enc_b1  = (const float*)d_in[5];
    const float* enc_W2  = (const float*)d_in[6];
    const float* enc_b2  = (const float*)d_in[7];
    const float* enc_lng = (const float*)d_in[8];
    const float* enc_lnb = (const float*)d_in[9];
    const float* enc_fg  = (const float*)d_in[10];
    const float* enc_fb  = (const float*)d_in[11];
    const float* dsW     = (const float*)d_in[12];
    const float* dsb     = (const float*)d_in[13];
    const float* dcW     = (const float*)d_in[14];
    const float* dcb     = (const float*)d_in[15];
    const float* dW1     = (const float*)d_in[16];
    const float* db1     = (const float*)d_in[17];
    const float* dW2     = (const float*)d_in[18];
    const float* db2     = (const float*)d_in[19];
    const float* dlng    = (const float*)d_in[20];
    const float* dlnb    = (const float*)d_in[21];
    const float* dfg     = (const float*)d_in[22];
    const float* dfb     = (const float*)d_in[23];
    const int*   src_mask = (const int*)d_in[24];
    const int*   tgt_mask = (const int*)d_in[25];
    float* out = (float*)d_out;

    float* scratch = nullptr;
    cudaGetSymbolAddress((void**)&scratch, g_scratch);

    float* X   = scratch + 0 * MEG;
    float* X2  = scratch + 1 * MEG;
    float* Qb  = scratch + 2 * MEG;  // Q/K/V contiguous for fused QKV gemm
    float* Kb  = scratch + 3 * MEG;
    float* Vb  = scratch + 4 * MEG;
    float* Ab  = scratch + 5 * MEG;
    float* H1  = scratch + 6 * MEG;   // 4M floats
    float* ATT = scratch + 10 * MEG;  // 8M floats
    float* ENC = scratch + 18 * MEG;

    const size_t SLAB      = (size_t)BB * HH * SS * SS;
    const size_t OFF_ENC   = (size_t)BB * SS * DD;
    const size_t OFF_SELF  = OFF_ENC + (size_t)LL * SLAB;
    const size_t OFF_CROSS = OFF_SELF + (size_t)LL * SLAB;
    const size_t TOTAL     = OFF_CROSS + (size_t)LL * SLAB;
    const bool full = ((size_t)out_size >= TOTAL);

    const size_t SC_SMEM = (size_t)(2 * 64 * 68 + 64 * 516) * sizeof(float);
    cudaFuncSetAttribute(attn_scores_tf32,
                         cudaFuncAttributeMaxDynamicSharedMemorySize, (int)SC_SMEM);

    dim3 gQKV(3072 / 128, MROWS / 64);   // 24 x 16 = 384 CTAs
    dim3 gKV(2048 / 128, MROWS / 64);    // 16 x 16 = 256
    dim3 gO(DD / 128, MROWS / 64);       // 8 x 16 = 128
    dim3 gF1(DFFF / 128, MROWS / 64);    // 32 x 16 = 512
    dim3 gS(SS / 64, BB * HH);
    dim3 gC(SS / 64, BB * HH);
    const long long WS = (long long)DD * DD;
    const long long CS = (long long)MEG;

    // ------------------------- Encoder -------------------------
    const float* cur = src;
    for (int l = 0; l < LL; l++) {
        const float* W  = enc_W + (size_t)l * 4 * DD * DD;
        const float* bb = enc_b + (size_t)l * 4 * DD;
        gemm_tf32<<<gQKV, 256>>>(cur, W, bb, Qb, MROWS, DD, DD, 0, WS, CS);
        float* adst = full ? out + OFF_ENC + (size_t)l * SLAB : ATT;
        attn_scores_tf32<<<gS, 256, SC_SMEM>>>(Qb, Kb, src_mask, 0, adst);
        attn_ctx_tf32<<<gC, 256>>>(adst, Vb, Qb);
        gemm_tf32<<<gO, 256>>>(Qb, W + 3 * DD * DD, bb + 3 * DD, Ab, MROWS, DD, DD, 0, 0, 0);
        add_ln_kernel<<<MROWS, 256>>>(cur, Ab, enc_lng + (size_t)l * 2 * DD,
                                      enc_lnb + (size_t)l * 2 * DD, X2);
        gemm_tf32<<<gF1, 256>>>(X2, enc_W1 + (size_t)l * DD * DFFF,
                                enc_b1 + (size_t)l * DFFF, H1, MROWS, DD, DFFF, 1, 0, 0);
        gemm_tf32<<<gO, 256>>>(H1, enc_W2 + (size_t)l * DFFF * DD,
                               enc_b2 + (size_t)l * DD, Ab, MROWS, DFFF, DD, 0, 0, 0);
        add_ln_kernel<<<MROWS, 256>>>(X2, Ab, enc_lng + (size_t)l * 2 * DD + DD,
                                      enc_lnb + (size_t)l * 2 * DD + DD, X);
        cur = X;
    }
    add_ln_kernel<<<MROWS, 256>>>(cur, nullptr, enc_fg, enc_fb, ENC);

    // ------------------------- Decoder -------------------------
    cur = tgt;
    for (int l = 0; l < LL; l++) {
        // self-attention (causal)
        const float* Ws = dsW + (size_t)l * 4 * DD * DD;
        const float* bs = dsb + (size_t)l * 4 * DD;
        gemm_tf32<<<gQKV, 256>>>(cur, Ws, bs, Qb, MROWS, DD, DD, 0, WS, CS);
        float* adst = full ? out + OFF_SELF + (size_t)l * SLAB : ATT;
        attn_scores_tf32<<<gS, 256, SC_SMEM>>>(Qb, Kb, tgt_mask, 1, adst);
        attn_ctx_tf32<<<gC, 256>>>(adst, Vb, Qb);
        gemm_tf32<<<gO, 256>>>(Qb, Ws + 3 * DD * DD, bs + 3 * DD, Ab, MROWS, DD, DD, 0, 0, 0);
        add_ln_kernel<<<MROWS, 256>>>(cur, Ab, dlng + (size_t)l * 3 * DD,
                                      dlnb + (size_t)l * 3 * DD, X);

        // cross-attention
        const float* Wc = dcW + (size_t)l * 4 * DD * DD;
        const float* bc = dcb + (size_t)l * 4 * DD;
        gemm_tf32<<<gO, 256>>>(X, Wc, bc, Qb, MROWS, DD, DD, 0, 0, 0);
        gemm_tf32<<<gKV, 256>>>(ENC, Wc + DD * DD, bc + DD, Kb, MROWS, DD, DD, 0, WS, CS);
        adst = full ? out + OFF_CROSS + (size_t)l * SLAB : ATT;
        attn_scores_tf32<<<gS, 256, SC_SMEM>>>(Qb, Kb, src_mask, 0, adst);
        attn_ctx_tf32<<<gC, 256>>>(adst, Vb, Qb);
        gemm_tf32<<<gO, 256>>>(Qb, Wc + 3 * DD * DD, bc + 3 * DD, Ab, MROWS, DD, DD, 0, 0, 0);
        add_ln_kernel<<<MROWS, 256>>>(X, Ab, dlng + (size_t)l * 3 * DD + DD,
                                      dlnb + (size_t)l * 3 * DD + DD, X2);

        // FFN
        gemm_tf32<<<gF1, 256>>>(X2, dW1 + (size_t)l * DD * DFFF,
                                db1 + (size_t)l * DFFF, H1, MROWS, DD, DFFF, 1, 0, 0);
        gemm_tf32<<<gO, 256>>>(H1, dW2 + (size_t)l * DFFF * DD,
                               db2 + (size_t)l * DD, Ab, MROWS, DFFF, DD, 0, 0, 0);
        add_ln_kernel<<<MROWS, 256>>>(X2, Ab, dlng + (size_t)l * 3 * DD + 2 * DD,
                                      dlnb + (size_t)l * 3 * DD + 2 * DD, X);
        cur = X;
    }
    add_ln_kernel<<<MROWS, 256>>>(cur, nullptr, dfg, dfb, out);
}

// round 4
// speedup vs baseline: 2.8168x; 1.1669x over previous
#include <cuda_runtime.h>
#include <cuda_bf16.h>
#include <cstdint>
#include <cstddef>

// ---------------------------------------------------------------------------
// Transformer forward (encoder-decoder), tf32 tensor cores, R4:
// double-buffered K-step-32 GEMM pipeline + 64x64 tiles for D-output GEMMs.
// ---------------------------------------------------------------------------

#define BB   2
#define SS   512
#define DD   1024
#define HH   16
#define DKK  64
#define DFFF 4096
#define LL   4
#define MROWS (BB*SS)          // 1024
#define EPSF 1e-5f
#define INV_SCALE 0.125f       // 1/sqrt(DK)

static const size_t MEG = 1u << 20;
__device__ __align__(16) float g_scratch[19u * (1u << 20)];

// ---------------------------------------------------------------------------
// tf32 helpers
// ---------------------------------------------------------------------------
__device__ __forceinline__ uint32_t f2t(float x) {
    uint32_t r; asm("cvt.rna.tf32.f32 %0, %1;" : "=r"(r) : "f"(x)); return r;
}
__device__ __forceinline__ void mma8(float* c, const uint32_t* a, const uint32_t* b) {
    asm volatile(
        "mma.sync.aligned.m16n8k8.row.col.f32.tf32.tf32.f32 "
        "{%0,%1,%2,%3}, {%4,%5,%6,%7}, {%8,%9}, {%0,%1,%2,%3};\n"
        : "+f"(c[0]), "+f"(c[1]), "+f"(c[2]), "+f"(c[3])
        : "r"(a[0]), "r"(a[1]), "r"(a[2]), "r"(a[3]), "r"(b[0]), "r"(b[1]));
}
__device__ __forceinline__ uint4 cvt4(float4 v) {
    uint4 u; u.x = f2t(v.x); u.y = f2t(v.y); u.z = f2t(v.z); u.w = f2t(v.w);
    return u;
}

// ---------------------------------------------------------------------------
// tf32 GEMM, templated tile: C[M, totalN] = A[M,K] @ W + bias, optional ReLU.
// Blocked-N support (fused QKV etc.): blk = colg/nb; W += blk*wstride;
// bias += blk*nb; C += blk*cstride; inner row strides of W and C are nb.
// TM x TN block tile, 8 warps in WR x WC grid (warp tile WM x WN).
// K-step 32, 2-stage smem double buffer, gmem->reg prefetch, 1 sync/iter.
// Grid: (totalN/TN, M/TM). Dynamic smem: 2*(TM*36 + 32*(TN+8))*4 bytes.
// ---------------------------------------------------------------------------
template<int TM, int TN, int WR, int WC>
__global__ __launch_bounds__(256, 2)
void gemm_tf32(const float* __restrict__ A, const float* __restrict__ W,
               const float* __restrict__ bias, float* __restrict__ C,
               int K, int nb, int relu,
               long long wstride, long long cstride)
{
    constexpr int ASTR = 36;            // A smem row stride (32 + 4 pad)
    constexpr int BSTR = TN + 8;        // B smem row stride
    constexpr int ASZ  = TM * ASTR;
    constexpr int BSZ  = 32 * BSTR;
    constexpr int STG  = ASZ + BSZ;
    constexpr int WM = TM / WR, WN = TN / WC;
    constexpr int MI = WM / 16, NJ = WN / 8;
    constexpr int NA = TM / 32;         // float4 A-loads per thread
    constexpr int NB = TN / 32;         // float4 B-loads per thread
    constexpr int BPR = TN / 4;         // threads per B row
    constexpr int BRP = 256 / BPR;      // B rows per pass

    extern __shared__ uint32_t smg[];

    const int t = threadIdx.x;
    const int lane = t & 31, w = t >> 5;
    const int g = lane >> 2, cc = lane & 3;
    const int wm = w / WC, wn = w % WC;
    const int row0 = blockIdx.y * TM;
    const int colg = blockIdx.x * TN;
    const int blk  = colg / nb;
    const int col0 = colg - blk * nb;
    const float* Wp = W + (size_t)blk * (size_t)wstride;
    const float* bp = bias + (size_t)blk * nb;
    float* Cp = C + (size_t)blk * (size_t)cstride;

    const int ar = t >> 3;              // 0..31
    const int ac = (t & 7) << 2;        // 0..28
    const int bk0 = t / BPR;
    const int bc  = (t % BPR) << 2;

    float4 aR[NA], bR[NB];

    auto loadAB = [&](int k0) {
#pragma unroll
        for (int i = 0; i < NA; i++)
            aR[i] = *(const float4*)&A[(size_t)(row0 + ar + i * 32) * K + k0 + ac];
#pragma unroll
        for (int i = 0; i < NB; i++)
            bR[i] = *(const float4*)&Wp[(size_t)(k0 + bk0 + i * BRP) * nb + col0 + bc];
    };
    auto storeAB = [&](int p) {
        uint32_t* as_ = smg + p * STG;
        uint32_t* bs_ = smg + p * STG + ASZ;
#pragma unroll
        for (int i = 0; i < NA; i++)
            *(uint4*)&as_[(ar + i * 32) * ASTR + ac] = cvt4(aR[i]);
#pragma unroll
        for (int i = 0; i < NB; i++)
            *(uint4*)&bs_[(bk0 + i * BRP) * BSTR + bc] = cvt4(bR[i]);
    };

    float acc[MI][NJ][4];
#pragma unroll
    for (int a_ = 0; a_ < MI; a_++)
#pragma unroll
        for (int b_ = 0; b_ < NJ; b_++)
#pragma unroll
            for (int c_ = 0; c_ < 4; c_++) acc[a_][b_][c_] = 0.f;

    const int NK = K >> 5;
    loadAB(0);
    storeAB(0);
    if (NK > 1) loadAB(32);
    __syncthreads();

    for (int it = 0; it < NK; it++) {
        const int p = it & 1;
        if (it + 1 < NK) storeAB(p ^ 1);
        if (it + 2 < NK) loadAB((it + 2) << 5);

        const uint32_t* as_ = smg + p * STG;
        const uint32_t* bs_ = smg + p * STG + ASZ;
        uint32_t af[MI][4], bf[NJ][2];
#pragma unroll
        for (int ks = 0; ks < 4; ks++) {
            const int kb = ks * 8 + cc;
#pragma unroll
            for (int mi = 0; mi < MI; mi++) {
                const int mb = wm * WM + mi * 16;
                af[mi][0] = as_[(mb + g) * ASTR + kb];
                af[mi][1] = as_[(mb + g + 8) * ASTR + kb];
                af[mi][2] = as_[(mb + g) * ASTR + kb + 4];
                af[mi][3] = as_[(mb + g + 8) * ASTR + kb + 4];
            }
#pragma unroll
            for (int nj = 0; nj < NJ; nj++) {
                const int nbase = wn * WN + nj * 8;
                bf[nj][0] = bs_[kb * BSTR + nbase + g];
                bf[nj][1] = bs_[(kb + 4) * BSTR + nbase + g];
            }
#pragma unroll
            for (int mi = 0; mi < MI; mi++)
#pragma unroll
                for (int nj = 0; nj < NJ; nj++)
                    mma8(acc[mi][nj], af[mi], bf[nj]);
        }
        __syncthreads();
    }

#pragma unroll
    for (int mi = 0; mi < MI; mi++) {
        const int r0 = row0 + wm * WM + mi * 16 + g;
#pragma unroll
        for (int nj = 0; nj < NJ; nj++) {
            const int c = col0 + wn * WN + nj * 8 + 2 * cc;
            const float b0v = bp[c], b1v = bp[c + 1];
            float v0 = acc[mi][nj][0] + b0v, v1 = acc[mi][nj][1] + b1v;
            float v2 = acc[mi][nj][2] + b0v, v3 = acc[mi][nj][3] + b1v;
            if (relu) {
                v0 = fmaxf(v0, 0.f); v1 = fmaxf(v1, 0.f);
                v2 = fmaxf(v2, 0.f); v3 = fmaxf(v3, 0.f);
            }
            *(float2*)&Cp[(size_t)r0 * nb + c]       = make_float2(v0, v1);
            *(float2*)&Cp[(size_t)(r0 + 8) * nb + c] = make_float2(v2, v3);
        }
    }
}

// ---------------------------------------------------------------------------
// Fused scores + mask + softmax (tf32 mma for Q.K^T, softmax in smem).
// Block: 64 q-rows x 512 keys; grid (S/64, B*H); 256 threads.
// ---------------------------------------------------------------------------
__global__ __launch_bounds__(256)
void attn_scores_tf32(const float* __restrict__ qf,
                      const float* __restrict__ kf,
                      const int* __restrict__ mask,
                      int causal,
                      float* __restrict__ attn)
{
    extern __shared__ float smemf[];
    uint32_t* Qs = (uint32_t*)smemf;        // 64*68
    uint32_t* Ks = Qs + 64 * 68;            // 64*68
    float* Ssm = smemf + 2 * 64 * 68;       // 64*516

    const int bh = blockIdx.y, b = bh >> 4, h = bh & 15;
    const int q0 = blockIdx.x * 64;
    const int t = threadIdx.x, lane = t & 31, w = t >> 5;
    const int g = lane >> 2, cc = lane & 3;
    const int qslot = w & 3, kslot = w >> 2;

#pragma unroll
    for (int i = 0; i < 4; i++) {
        const int idx = t + i * 256;
        const int r = idx >> 4, cq = (idx & 15) << 2;
        float4 v = *(const float4*)&qf[(size_t)(b * SS + q0 + r) * DD + h * DKK + cq];
        *(uint4*)&Qs[r * 68 + cq] = cvt4(v);
    }

    for (int kt = 0; kt < 8; kt++) {
        __syncthreads();
#pragma unroll
        for (int i = 0; i < 4; i++) {
            const int idx = t + i * 256;
            const int r = idx >> 4, cq = (idx & 15) << 2;
            float4 v = *(const float4*)&kf[(size_t)(b * SS + kt * 64 + r) * DD + h * DKK + cq];
            *(uint4*)&Ks[r * 68 + cq] = cvt4(v);
        }
        __syncthreads();

        float acc[4][4] = {};
        uint32_t af[4];
#pragma unroll
        for (int ks = 0; ks < 8; ks++) {
            const int kb = ks * 8 + cc;
            const int mb = qslot * 16;
            af[0] = Qs[(mb + g) * 68 + kb];
            af[1] = Qs[(mb + g + 8) * 68 + kb];
            af[2] = Qs[(mb + g) * 68 + kb + 4];
            af[3] = Qs[(mb + g + 8) * 68 + kb + 4];
#pragma unroll
            for (int nj = 0; nj < 4; nj++) {
                const int nbase = kslot * 32 + nj * 8;
                uint32_t bf[2];
                bf[0] = Ks[(nbase + g) * 68 + kb];
                bf[1] = Ks[(nbase + g) * 68 + kb + 4];
                mma8(acc[nj], af, bf);
            }
        }
#pragma unroll
        for (int nj = 0; nj < 4; nj++) {
            const int colb = kt * 64 + kslot * 32 + nj * 8 + 2 * cc;
            const int rr = qslot * 16 + g;
            *(float2*)&Ssm[rr * 516 + colb]       = make_float2(acc[nj][0], acc[nj][1]);
            *(float2*)&Ssm[(rr + 8) * 516 + colb] = make_float2(acc[nj][2], acc[nj][3]);
        }
    }
    __syncthreads();

    for (int i = 0; i < 8; i++) {
        const int rloc = w * 8 + i;
        const int q = q0 + rloc;
        float vals[16];
        float mx = -1e30f;
#pragma unroll
        for (int j = 0; j < 16; j++) {
            const int col = lane + j * 32;
            float v = Ssm[rloc * 516 + col] * INV_SCALE;
            const int m = causal ? mask[((size_t)b * SS + q) * SS + col]
                                 : mask[(size_t)b * SS + col];
            if (m == 0) v = -1e9f;
            vals[j] = v;
            mx = fmaxf(mx, v);
        }
#pragma unroll
        for (int o = 16; o > 0; o >>= 1)
            mx = fmaxf(mx, __shfl_xor_sync(0xffffffffu, mx, o));
        float sum = 0.0f;
#pragma unroll
        for (int j = 0; j < 16; j++) {
            vals[j] = expf(vals[j] - mx);
            sum += vals[j];
        }
#pragma unroll
        for (int o = 16; o > 0; o >>= 1)
            sum += __shfl_xor_sync(0xffffffffu, sum, o);
        const float inv = 1.0f / sum;
        float* dst = attn + ((size_t)bh * SS + q) * SS;
#pragma unroll
        for (int j = 0; j < 16; j++)
            dst[lane + j * 32] = vals[j] * inv;
    }
}

// ---------------------------------------------------------------------------
// Context: ctx[q,d] = sum_k attn[q,k] * V[k,d], tf32 mma.
// ---------------------------------------------------------------------------
__global__ __launch_bounds__(256)
void attn_ctx_tf32(const float* __restrict__ attn,
                   const float* __restrict__ vf,
                   float* __restrict__ ctx)
{
    __shared__ uint32_t As[64 * 20];
    __shared__ uint32_t Vs[16 * 72];
    const int bh = blockIdx.y, b = bh >> 4, h = bh & 15;
    const int q0 = blockIdx.x * 64;
    const int t = threadIdx.x, lane = t & 31, w = t >> 5;
    const int g = lane >> 2, cc = lane & 3;
    const int qslot = w & 3, dslot = w >> 2;
    const float* Ap = attn + (size_t)bh * SS * SS;
    const float* Vp = vf + (size_t)b * SS * DD + h * DKK;

    float acc[4][4] = {};
    for (int k0 = 0; k0 < SS; k0 += 16) {
        {
            const int r = t >> 2, ak = (t & 3) << 2;
            float4 v = *(const float4*)&Ap[(size_t)(q0 + r) * SS + k0 + ak];
            *(uint4*)&As[r * 20 + ak] = cvt4(v);
        }
        {
            const int kr = t >> 4, cq = (t & 15) << 2;
            float4 v = *(const float4*)&Vp[(size_t)(k0 + kr) * DD + cq];
            *(uint4*)&Vs[kr * 72 + cq] = cvt4(v);
        }
        __syncthreads();

        uint32_t af[4], bf[2];
#pragma unroll
        for (int ks = 0; ks < 2; ks++) {
            const int kb = ks * 8 + cc;
            const int mb = qslot * 16;
            af[0] = As[(mb + g) * 20 + kb];
            af[1] = As[(mb + g + 8) * 20 + kb];
            af[2] = As[(mb + g) * 20 + kb + 4];
            af[3] = As[(mb + g + 8) * 20 + kb + 4];
#pragma unroll
            for (int nj = 0; nj < 4; nj++) {
                const int nbase = dslot * 32 + nj * 8;
                bf[0] = Vs[kb * 72 + nbase + g];
                bf[1] = Vs[(kb + 4) * 72 + nbase + g];
                mma8(acc[nj], af, bf);
            }
        }
        __syncthreads();
    }

    float* Cp = ctx + (size_t)b * SS * DD + h * DKK;
#pragma unroll
    for (int nj = 0; nj < 4; nj++) {
        const int c = dslot * 32 + nj * 8 + 2 * cc;
        const int r = q0 + qslot * 16 + g;
        *(float2*)&Cp[(size_t)r * DD + c]       = make_float2(acc[nj][0], acc[nj][1]);
        *(float2*)&Cp[(size_t)(r + 8) * DD + c] = make_float2(acc[nj][2], acc[nj][3]);
    }
}

// ---------------------------------------------------------------------------
// y = LayerNorm(x + a). a may be nullptr. One block per row (D=1024).
// ---------------------------------------------------------------------------
__global__ __launch_bounds__(256)
void add_ln_kernel(const float* __restrict__ x,
                   const float* __restrict__ a,
                   const float* __restrict__ g,
                   const float* __restrict__ bt,
                   float* __restrict__ y)
{
    const int row = blockIdx.x;
    const int t = threadIdx.x;
    __shared__ float red[256];

    float v[4];
#pragma unroll
    for (int i = 0; i < 4; i++) {
        const int c = t + i * 256;
        float vv = x[(size_t)row * DD + c];
        if (a) vv += a[(size_t)row * DD + c];
        v[i] = vv;
    }
    float s = v[0] + v[1] + v[2] + v[3];
    red[t] = s;
    __syncthreads();
    for (int o = 128; o > 0; o >>= 1) {
        if (t < o) red[t] += red[t + o];
        __syncthreads();
    }
    const float mean = red[0] * (1.0f / DD);
    __syncthreads();

    float s2 = 0.0f;
#pragma unroll
    for (int i = 0; i < 4; i++) {
        const float d = v[i] - mean;
        s2 += d * d;
    }
    red[t] = s2;
    __syncthreads();
    for (int o = 128; o > 0; o >>= 1) {
        if (t < o) red[t] += red[t + o];
        __syncthreads();
    }
    const float var = red[0] * (1.0f / DD);
    const float inv = rsqrtf(var + EPSF);

#pragma unroll
    for (int i = 0; i < 4; i++) {
        const int c = t + i * 256;
        y[(size_t)row * DD + c] = g[c] * (v[i] - mean) * inv + bt[c];
    }
}

// ---------------------------------------------------------------------------
// Host orchestration
// ---------------------------------------------------------------------------
extern "C" void kernel_launch(void* const* d_in, const int* in_sizes, int n_in,
                              void* d_out, int out_size)
{
    const float* src     = (const float*)d_in[0];
    const float* tgt     = (const float*)d_in[1];
    const float* enc_W   = (const float*)d_in[2];
    const float* enc_b   = (const float*)d_in[3];
    const float* enc_W1  = (const float*)d_in[4];
    const float* enc_b1  = (const float*)d_in[5];
    const float* enc_W2  = (const float*)d_in[6];
    const float* enc_b2  = (const float*)d_in[7];
    const float* enc_lng = (const float*)d_in[8];
    const float* enc_lnb = (const float*)d_in[9];
    const float* enc_fg  = (const float*)d_in[10];
    const float* enc_fb  = (const float*)d_in[11];
    const float* dsW     = (const float*)d_in[12];
    const float* dsb     = (const float*)d_in[13];
    const float* dcW     = (const float*)d_in[14];
    const float* dcb     = (const float*)d_in[15];
    const float* dW1     = (const float*)d_in[16];
    const float* db1     = (const float*)d_in[17];
    const float* dW2     = (const float*)d_in[18];
    const float* db2     = (const float*)d_in[19];
    const float* dlng    = (const float*)d_in[20];
    const float* dlnb    = (const float*)d_in[21];
    const float* dfg     = (const float*)d_in[22];
    const float* dfb     = (const float*)d_in[23];
    const int*   src_mask = (const int*)d_in[24];
    const int*   tgt_mask = (const int*)d_in[25];
    float* out = (float*)d_out;

    float* scratch = nullptr;
    cudaGetSymbolAddress((void**)&scratch, g_scratch);

    float* X   = scratch + 0 * MEG;
    float* X2  = scratch + 1 * MEG;
    float* Qb  = scratch + 2 * MEG;  // Q/K/V contiguous for fused QKV gemm
    float* Kb  = scratch + 3 * MEG;
    float* Vb  = scratch + 4 * MEG;
    float* Ab  = scratch + 5 * MEG;
    float* H1  = scratch + 6 * MEG;   // 4M floats
    float* ATT = scratch + 10 * MEG;  // 8M floats
    float* ENC = scratch + 18 * MEG;

    const size_t SLAB      = (size_t)BB * HH * SS * SS;
    const size_t OFF_ENC   = (size_t)BB * SS * DD;
    const size_t OFF_SELF  = OFF_ENC + (size_t)LL * SLAB;
    const size_t OFF_CROSS = OFF_SELF + (size_t)LL * SLAB;
    const size_t TOTAL     = OFF_CROSS + (size_t)LL * SLAB;
    const bool full = ((size_t)out_size >= TOTAL);

    // Dynamic smem sizes for the two GEMM configs
    const int SM_A = 2 * (64 * 36 + 32 * 136) * 4;  // 53248 B (TN=128)
    const int SM_B = 2 * (64 * 36 + 32 * 72) * 4;   // 36864 B (TN=64)
    auto gemmA = gemm_tf32<64, 128, 2, 4>;
    auto gemmB = gemm_tf32<64, 64, 4, 2>;
    cudaFuncSetAttribute(gemmA, cudaFuncAttributeMaxDynamicSharedMemorySize, SM_A);
    cudaFuncSetAttribute(gemmB, cudaFuncAttributeMaxDynamicSharedMemorySize, SM_B);

    const size_t SC_SMEM = (size_t)(2 * 64 * 68 + 64 * 516) * sizeof(float);
    cudaFuncSetAttribute(attn_scores_tf32,
                         cudaFuncAttributeMaxDynamicSharedMemorySize, (int)SC_SMEM);

    dim3 gQKV(3072 / 128, MROWS / 64);   // 24 x 16 = 384 CTAs (config A)
    dim3 gKV(2048 / 128, MROWS / 64);    // 16 x 16 = 256      (config A)
    dim3 gF1(DFFF / 128, MROWS / 64);    // 32 x 16 = 512      (config A)
    dim3 gO(DD / 64, MROWS / 64);        // 16 x 16 = 256      (config B)
    dim3 gS(SS / 64, BB * HH);
    dim3 gC(SS / 64, BB * HH);
    const long long WS = (long long)DD * DD;
    const long long CS = (long long)MEG;

    // ------------------------- Encoder -------------------------
    const float* cur = src;
    for (int l = 0; l < LL; l++) {
        const float* W  = enc_W + (size_t)l * 4 * DD * DD;
        const float* bb = enc_b + (size_t)l * 4 * DD;
        gemmA<<<gQKV, 256, SM_A>>>(cur, W, bb, Qb, DD, DD, 0, WS, CS);
        float* adst = full ? out + OFF_ENC + (size_t)l * SLAB : ATT;
        attn_scores_tf32<<<gS, 256, SC_SMEM>>>(Qb, Kb, src_mask, 0, adst);
        attn_ctx_tf32<<<gC, 256>>>(adst, Vb, Qb);
        gemmB<<<gO, 256, SM_B>>>(Qb, W + 3 * DD * DD, bb + 3 * DD, Ab, DD, DD, 0, 0, 0);
        add_ln_kernel<<<MROWS, 256>>>(cur, Ab, enc_lng + (size_t)l * 2 * DD,
                                      enc_lnb + (size_t)l * 2 * DD, X2);
        gemmA<<<gF1, 256, SM_A>>>(X2, enc_W1 + (size_t)l * DD * DFFF,
                                  enc_b1 + (size_t)l * DFFF, H1, DD, DFFF, 1, 0, 0);
        gemmB<<<gO, 256, SM_B>>>(H1, enc_W2 + (size_t)l * DFFF * DD,
                                 enc_b2 + (size_t)l * DD, Ab, DFFF, DD, 0, 0, 0);
        add_ln_kernel<<<MROWS, 256>>>(X2, Ab, enc_lng + (size_t)l * 2 * DD + DD,
                                      enc_lnb + (size_t)l * 2 * DD + DD, X);
        cur = X;
    }
    add_ln_kernel<<<MROWS, 256>>>(cur, nullptr, enc_fg, enc_fb, ENC);

    // ------------------------- Decoder -------------------------
    cur = tgt;
    for (int l = 0; l < LL; l++) {
        // self-attention (causal)
        const float* Ws = dsW + (size_t)l * 4 * DD * DD;
        const float* bs = dsb + (size_t)l * 4 * DD;
        gemmA<<<gQKV, 256, SM_A>>>(cur, Ws, bs, Qb, DD, DD, 0, WS, CS);
        float* adst = full ? out + OFF_SELF + (size_t)l * SLAB : ATT;
        attn_scores_tf32<<<gS, 256, SC_SMEM>>>(Qb, Kb, tgt_mask, 1, adst);
        attn_ctx_tf32<<<gC, 256>>>(adst, Vb, Qb);
        gemmB<<<gO, 256, SM_B>>>(Qb, Ws + 3 * DD * DD, bs + 3 * DD, Ab, DD, DD, 0, 0, 0);
        add_ln_kernel<<<MROWS, 256>>>(cur, Ab, dlng + (size_t)l * 3 * DD,
                                      dlnb + (size_t)l * 3 * DD, X);

        // cross-attention
        const float* Wc = dcW + (size_t)l * 4 * DD * DD;
        const float* bc = dcb + (size_t)l * 4 * DD;
        gemmB<<<gO, 256, SM_B>>>(X, Wc, bc, Qb, DD, DD, 0, 0, 0);
        gemmA<<<gKV, 256, SM_A>>>(ENC, Wc + DD * DD, bc + DD, Kb, DD, DD, 0, WS, CS);
        adst = full ? out + OFF_CROSS + (size_t)l * SLAB : ATT;
        attn_scores_tf32<<<gS, 256, SC_SMEM>>>(Qb, Kb, src_mask, 0, adst);
        attn_ctx_tf32<<<gC, 256>>>(adst, Vb, Qb);
        gemmB<<<gO, 256, SM_B>>>(Qb, Wc + 3 * DD * DD, bc + 3 * DD, Ab, DD, DD, 0, 0, 0);
        add_ln_kernel<<<MROWS, 256>>>(X, Ab, dlng + (size_t)l * 3 * DD + DD,
                                      dlnb + (size_t)l * 3 * DD + DD, X2);

        // FFN
        gemmA<<<gF1, 256, SM_A>>>(X2, dW1 + (size_t)l * DD * DFFF,
                                  db1 + (size_t)l * DFFF, H1, DD, DFFF, 1, 0, 0);
        gemmB<<<gO, 256, SM_B>>>(H1, dW2 + (size_t)l * DFFF * DD,
                                 db2 + (size_t)l * DD, Ab, DFFF, DD, 0, 0, 0);
        add_ln_kernel<<<MROWS, 256>>>(X2, Ab, dlng + (size_t)l * 3 * DD + 2 * DD,
                                      dlnb + (size_t)l * 3 * DD + 2 * DD, X);
        cur = X;
    }
    add_ln_kernel<<<MROWS, 256>>>(cur, nullptr, dfg, dfb, out);
}